// round 2
// baseline (speedup 1.0000x reference)
#include <cuda_runtime.h>
#include <cuda_fp16.h>
#include <cstdint>
#include <cstddef>

// ---------------------------------------------------------------------------
// Problem dims (fixed by setup_inputs): y[4096,4096] = scale * x @ W^T + bias
// ---------------------------------------------------------------------------
#define TOKENS 4096
#define KDIM   4096
#define ODIM   4096

// GEMM tile config (legacy mma.sync path: sm_103 plain target, no tcgen05)
#define BM 128
#define BN 256
#define BK 64
#define STAGES 3
#define KT (KDIM / BK)              // 64 k-iterations

#define A_BYTES (BM * BK * 2)       // 16384
#define B_BYTES (BN * BK * 2)       // 32768
#define STAGE_BYTES (A_BYTES + B_BYTES)      // 49152
#define SMEM_TOTAL (STAGES * STAGE_BYTES)    // 147456

// ---------------------------------------------------------------------------
// Scratch (device globals: allocation-free per harness rules)
// ---------------------------------------------------------------------------
__device__ __half g_xh[(size_t)TOKENS * KDIM];   // x rounded to fp16
__device__ __half g_w [(size_t)ODIM   * KDIM];   // ternary weights in fp16

// ---------------------------------------------------------------------------
// Helpers
// ---------------------------------------------------------------------------
__device__ __forceinline__ uint32_t smem_u32(const void* p) {
    uint32_t a;
    asm("{ .reg .u64 t; cvta.to.shared.u64 t, %1; cvt.u32.u64 %0, t; }" : "=r"(a) : "l"(p));
    return a;
}

// SW128 swizzle (Swizzle<3,4,3>): conflict-free ldmatrix on 128B rows
__device__ __forceinline__ uint32_t sw128(uint32_t off) {
    return off ^ ((off >> 3) & 0x70);
}

__device__ __forceinline__ void cp16(uint32_t dst, const void* src) {
    asm volatile("cp.async.cg.shared.global [%0], [%1], 16;" :: "r"(dst), "l"(src) : "memory");
}

__device__ __forceinline__ void ldsm4(uint32_t (&r)[4], uint32_t addr) {
    asm volatile("ldmatrix.sync.aligned.m8n8.x4.shared.b16 {%0,%1,%2,%3}, [%4];"
                 : "=r"(r[0]), "=r"(r[1]), "=r"(r[2]), "=r"(r[3]) : "r"(addr));
}

__device__ __forceinline__ void mma16816(float* c, const uint32_t* a, uint32_t b0, uint32_t b1) {
    asm volatile(
        "mma.sync.aligned.m16n8k16.row.col.f32.f16.f16.f32 "
        "{%0,%1,%2,%3}, {%4,%5,%6,%7}, {%8,%9}, {%0,%1,%2,%3};"
        : "+f"(c[0]), "+f"(c[1]), "+f"(c[2]), "+f"(c[3])
        : "r"(a[0]), "r"(a[1]), "r"(a[2]), "r"(a[3]), "r"(b0), "r"(b1));
}

// ---------------------------------------------------------------------------
// Prologue kernel 1: x fp32 -> fp16 (round-to-nearest; |x| ~ N(0,1) fits fp16)
// ---------------------------------------------------------------------------
__global__ void __launch_bounds__(256) tofp16_x_kernel(const float* __restrict__ x) {
    size_t i = ((size_t)blockIdx.x * 256 + threadIdx.x) * 8;
    float4 a = *(const float4*)(x + i);
    float4 b = *(const float4*)(x + i + 4);
    float v[8] = {a.x, a.y, a.z, a.w, b.x, b.y, b.z, b.w};
    union { __half h[8]; uint4 u; } H;
#pragma unroll
    for (int k = 0; k < 8; k++) H.h[k] = __float2half_rn(v[k]);
    *(uint4*)(g_xh + i) = H.u;
}

// ---------------------------------------------------------------------------
// Prologue kernel 2: bitmasks -> fp16 W[ODIM][KDIM].
// bit (128>>k) of mask byte j covers input column j*8+k  (MSB-first)
// ---------------------------------------------------------------------------
__global__ void __launch_bounds__(256) unpack_w_kernel(const int* __restrict__ pm,
                                                       const int* __restrict__ nm) {
    int id = blockIdx.x * 256 + threadIdx.x;     // [0, ODIM * KDIM/8)
    int p = pm[id], n = nm[id];
    union { unsigned short h[8]; uint4 u; } W;
#pragma unroll
    for (int k = 0; k < 8; k++) {
        int pb = (p >> (7 - k)) & 1;
        int nb = (n >> (7 - k)) & 1;
        int b = pb - nb;                                  // {-1, 0, +1}
        W.h[k] = (b == 0) ? (unsigned short)0
                          : ((b > 0) ? (unsigned short)0x3C00   // +1.0h
                                     : (unsigned short)0xBC00); // -1.0h
    }
    *(uint4*)(g_w + (size_t)id * 8) = W.u;
}

// ---------------------------------------------------------------------------
// Stage loader: A[128x64] + B[256x64] fp16 into SW128 smem (256 threads)
// ---------------------------------------------------------------------------
__device__ __forceinline__ void load_stage(uint32_t sbase, int m0, int n0, int kb, int tid) {
#pragma unroll
    for (int i = 0; i < 4; i++) {                // A: 1024 x 16B chunks
        int idx = tid + i * 256;
        int r = idx >> 3, c = idx & 7;
        cp16(sbase + sw128((uint32_t)(r * 128 + c * 16)),
             g_xh + (size_t)(m0 + r) * KDIM + kb + c * 8);
    }
#pragma unroll
    for (int i = 0; i < 8; i++) {                // B: 2048 x 16B chunks
        int idx = tid + i * 256;
        int r = idx >> 3, c = idx & 7;
        cp16(sbase + A_BYTES + sw128((uint32_t)(r * 128 + c * 16)),
             g_w + (size_t)(n0 + r) * KDIM + kb + c * 8);
    }
}

// ---------------------------------------------------------------------------
// Fragment loader: one k16 step for a 64x64 warp tile
// A frags from [m][k] smem, B frags from [n][k] smem, both via non-trans ldmatrix
// ---------------------------------------------------------------------------
__device__ __forceinline__ void load_frags(uint32_t a_base, uint32_t b_base, int kt,
                                           int wm, int wn, int lane,
                                           uint32_t (&A)[4][4], uint32_t (&B)[4][4]) {
    const int mat = lane >> 3, lr = lane & 7;
#pragma unroll
    for (int mt = 0; mt < 4; mt++) {
        int row = wm + mt * 16 + ((mat & 1) << 3) + lr;
        uint32_t off = (uint32_t)(row * 128 + kt * 32 + ((mat >> 1) << 4));
        ldsm4(A[mt], a_base + sw128(off));
    }
#pragma unroll
    for (int nt = 0; nt < 4; nt++) {
        int row = wn + nt * 16 + ((mat >> 1) << 3) + lr;
        uint32_t off = (uint32_t)(row * 128 + kt * 32 + ((mat & 1) << 4));
        ldsm4(B[nt], b_base + sw128(off));
    }
}

// ---------------------------------------------------------------------------
// Main GEMM: C[128,256] = A[128,4096] @ B[256,4096]^T, fp16 in, fp32 acc
// 256 threads = 8 warps (2m x 4n), warp tile 64x64
// ---------------------------------------------------------------------------
__global__ void __launch_bounds__(256, 1)
ternary_gemm_kernel(const float* __restrict__ scale_p,
                    const float* __restrict__ bias,
                    float* __restrict__ out) {
    extern __shared__ char smem[];
    const uint32_t sb = smem_u32(smem);
    const int tid = threadIdx.x;
    const int lane = tid & 31, wid = tid >> 5;
    const int m0 = blockIdx.y * BM;
    const int n0 = blockIdx.x * BN;
    const int wm = (wid >> 2) * 64, wn = (wid & 3) * 64;

    float acc[4][8][4];
#pragma unroll
    for (int i = 0; i < 4; i++)
#pragma unroll
        for (int j = 0; j < 8; j++)
#pragma unroll
            for (int c = 0; c < 4; c++) acc[i][j][c] = 0.0f;

    // ---- pipeline prologue ----
#pragma unroll
    for (int s = 0; s < STAGES - 1; s++) {
        load_stage(sb + s * STAGE_BYTES, m0, n0, s * BK, tid);
        asm volatile("cp.async.commit_group;" ::: "memory");
    }
    asm volatile("cp.async.wait_group %0;" :: "n"(STAGES - 2) : "memory");
    __syncthreads();

    int rs = 0, ws = STAGES - 1;

    for (int k = 0; k < KT; k++) {
        // prefetch stage k+STAGES-1
        if (k + STAGES - 1 < KT)
            load_stage(sb + ws * STAGE_BYTES, m0, n0, (k + STAGES - 1) * BK, tid);
        asm volatile("cp.async.commit_group;" ::: "memory");

        // compute on stage rs (4 x k16 steps, double-buffered fragments)
        const uint32_t abase = sb + rs * STAGE_BYTES;
        const uint32_t bbase = abase + A_BYTES;
        uint32_t Af[2][4][4], Bf[2][4][4];
        load_frags(abase, bbase, 0, wm, wn, lane, Af[0], Bf[0]);
#pragma unroll
        for (int kt = 0; kt < 4; kt++) {
            if (kt < 3)
                load_frags(abase, bbase, kt + 1, wm, wn, lane, Af[(kt + 1) & 1], Bf[(kt + 1) & 1]);
            const int cur = kt & 1;
#pragma unroll
            for (int mt = 0; mt < 4; mt++) {
#pragma unroll
                for (int nt = 0; nt < 4; nt++) {
                    mma16816(acc[mt][nt * 2],     Af[cur][mt], Bf[cur][nt][0], Bf[cur][nt][1]);
                    mma16816(acc[mt][nt * 2 + 1], Af[cur][mt], Bf[cur][nt][2], Bf[cur][nt][3]);
                }
            }
        }

        ws = rs;
        rs = (rs + 1) % STAGES;
        asm volatile("cp.async.wait_group %0;" :: "n"(STAGES - 2) : "memory");
        __syncthreads();
    }

    // ---- epilogue: y = scale * acc + bias, direct float2 stores ----
    const float scale = __ldg(scale_p);
#pragma unroll
    for (int mt = 0; mt < 4; mt++) {
        const int row = m0 + wm + mt * 16 + (lane >> 2);
#pragma unroll
        for (int nt8 = 0; nt8 < 8; nt8++) {
            const int col = n0 + wn + nt8 * 8 + (lane & 3) * 2;
            const float2 bb = *(const float2*)(bias + col);
            float2 v0, v1;
            v0.x = fmaf(scale, acc[mt][nt8][0], bb.x);
            v0.y = fmaf(scale, acc[mt][nt8][1], bb.y);
            v1.x = fmaf(scale, acc[mt][nt8][2], bb.x);
            v1.y = fmaf(scale, acc[mt][nt8][3], bb.y);
            *(float2*)(out + (size_t)row * ODIM + col)       = v0;
            *(float2*)(out + (size_t)(row + 8) * ODIM + col) = v1;
        }
    }
}

// ---------------------------------------------------------------------------
// Launch
// ---------------------------------------------------------------------------
extern "C" void kernel_launch(void* const* d_in, const int* in_sizes, int n_in,
                              void* d_out, int out_size) {
    const float* x     = (const float*)d_in[0];
    const int*   pm    = (const int*)d_in[1];
    const int*   nm    = (const int*)d_in[2];
    const float* scale = (const float*)d_in[3];
    const float* bias  = (const float*)d_in[4];
    float* out = (float*)d_out;

    (void)in_sizes; (void)n_in; (void)out_size;

    // 1) x -> fp16
    tofp16_x_kernel<<<(int)(((size_t)TOKENS * KDIM) / (256 * 8)), 256>>>(x);
    // 2) unpack ternary masks -> fp16 W
    unpack_w_kernel<<<(ODIM * (KDIM / 8)) / 256, 256>>>(pm, nm);
    // 3) pipelined mma.sync GEMM + fused epilogue
    cudaFuncSetAttribute(ternary_gemm_kernel,
                         cudaFuncAttributeMaxDynamicSharedMemorySize, SMEM_TOTAL);
    dim3 grid(ODIM / BN, TOKENS / BM);
    ternary_gemm_kernel<<<grid, 256, SMEM_TOTAL>>>(scale, bias, out);
}

// round 3
// speedup vs baseline: 1.1493x; 1.1493x over previous
#include <cuda_runtime.h>
#include <cuda_fp16.h>
#include <cstdint>
#include <cstddef>

// ---------------------------------------------------------------------------
// Problem dims: y[4096,4096] = scale * x @ W^T + bias
// ---------------------------------------------------------------------------
#define TOKENS 4096
#define KDIM   4096
#define ODIM   4096

// GEMM tile config (legacy mma.sync path; plain sm_103 target, no tcgen05)
#define BM 128
#define BN 256
#define BK 64
#define STAGES 3
#define KT (KDIM / BK)              // 64 k-iterations

#define A_BYTES (BM * BK * 2)       // 16384
#define B_BYTES (BN * BK * 2)       // 32768
#define STAGE_BYTES (A_BYTES + B_BYTES)      // 49152
#define SMEM_TOTAL (STAGES * STAGE_BYTES)    // 147456

#define NTHREADS 512                // 16 warps: 2(m) x 8(n), warp tile 64x32

// ---------------------------------------------------------------------------
// Scratch (device globals: allocation-free per harness rules)
// ---------------------------------------------------------------------------
__device__ __half g_xh[(size_t)TOKENS * KDIM];   // x rounded to fp16
__device__ __half g_w [(size_t)ODIM   * KDIM];   // ternary weights in fp16

// ---------------------------------------------------------------------------
// Helpers
// ---------------------------------------------------------------------------
__device__ __forceinline__ uint32_t smem_u32(const void* p) {
    uint32_t a;
    asm("{ .reg .u64 t; cvta.to.shared.u64 t, %1; cvt.u32.u64 %0, t; }" : "=r"(a) : "l"(p));
    return a;
}

// SW128 swizzle (Swizzle<3,4,3>): conflict-free ldmatrix on 128B rows
__device__ __forceinline__ uint32_t sw128(uint32_t off) {
    return off ^ ((off >> 3) & 0x70);
}

__device__ __forceinline__ void cp16(uint32_t dst, const void* src) {
    asm volatile("cp.async.cg.shared.global [%0], [%1], 16;" :: "r"(dst), "l"(src) : "memory");
}

__device__ __forceinline__ void ldsm4(uint32_t (&r)[4], uint32_t addr) {
    asm volatile("ldmatrix.sync.aligned.m8n8.x4.shared.b16 {%0,%1,%2,%3}, [%4];"
                 : "=r"(r[0]), "=r"(r[1]), "=r"(r[2]), "=r"(r[3]) : "r"(addr));
}

// fp16-accumulate HMMA (2x rate of fp32-acc on the legacy tensor pipe)
__device__ __forceinline__ void mma16816_h(uint32_t* d, const uint32_t* a,
                                           uint32_t b0, uint32_t b1) {
    asm volatile(
        "mma.sync.aligned.m16n8k16.row.col.f16.f16.f16.f16 "
        "{%0,%1}, {%2,%3,%4,%5}, {%6,%7}, {%0,%1};"
        : "+r"(d[0]), "+r"(d[1])
        : "r"(a[0]), "r"(a[1]), "r"(a[2]), "r"(a[3]), "r"(b0), "r"(b1));
}

// ---------------------------------------------------------------------------
// Prologue kernel 1: x fp32 -> fp16 (round-to-nearest)
// ---------------------------------------------------------------------------
__global__ void __launch_bounds__(256) tofp16_x_kernel(const float* __restrict__ x) {
    size_t i = ((size_t)blockIdx.x * 256 + threadIdx.x) * 8;
    float4 a = *(const float4*)(x + i);
    float4 b = *(const float4*)(x + i + 4);
    float v[8] = {a.x, a.y, a.z, a.w, b.x, b.y, b.z, b.w};
    union { __half h[8]; uint4 u; } H;
#pragma unroll
    for (int k = 0; k < 8; k++) H.h[k] = __float2half_rn(v[k]);
    *(uint4*)(g_xh + i) = H.u;
}

// ---------------------------------------------------------------------------
// Prologue kernel 2: bitmasks -> fp16 W[ODIM][KDIM] (MSB-first bit order)
// ---------------------------------------------------------------------------
__global__ void __launch_bounds__(256) unpack_w_kernel(const int* __restrict__ pm,
                                                       const int* __restrict__ nm) {
    int id = blockIdx.x * 256 + threadIdx.x;     // [0, ODIM * KDIM/8)
    int p = pm[id], n = nm[id];
    union { unsigned short h[8]; uint4 u; } W;
#pragma unroll
    for (int k = 0; k < 8; k++) {
        int pb = (p >> (7 - k)) & 1;
        int nb = (n >> (7 - k)) & 1;
        int b = pb - nb;                                  // {-1, 0, +1}
        W.h[k] = (b == 0) ? (unsigned short)0
                          : ((b > 0) ? (unsigned short)0x3C00   // +1.0h
                                     : (unsigned short)0xBC00); // -1.0h
    }
    *(uint4*)(g_w + (size_t)id * 8) = W.u;
}

// ---------------------------------------------------------------------------
// Stage loader: A[128x64] + B[256x64] fp16 into SW128 smem (512 threads)
// ---------------------------------------------------------------------------
__device__ __forceinline__ void load_stage(uint32_t sbase, int m0, int n0, int kb, int tid) {
#pragma unroll
    for (int i = 0; i < 2; i++) {                // A: 1024 x 16B chunks
        int idx = tid + i * NTHREADS;
        int r = idx >> 3, c = idx & 7;
        cp16(sbase + sw128((uint32_t)(r * 128 + c * 16)),
             g_xh + (size_t)(m0 + r) * KDIM + kb + c * 8);
    }
#pragma unroll
    for (int i = 0; i < 4; i++) {                // B: 2048 x 16B chunks
        int idx = tid + i * NTHREADS;
        int r = idx >> 3, c = idx & 7;
        cp16(sbase + A_BYTES + sw128((uint32_t)(r * 128 + c * 16)),
             g_w + (size_t)(n0 + r) * KDIM + kb + c * 8);
    }
}

// ---------------------------------------------------------------------------
// Fragment loader: one k16 step for a 64x32 warp tile
// ---------------------------------------------------------------------------
__device__ __forceinline__ void load_frags(uint32_t a_base, uint32_t b_base, int kt,
                                           int wm, int wn, int lane,
                                           uint32_t (&A)[4][4], uint32_t (&B)[2][4]) {
    const int mat = lane >> 3, lr = lane & 7;
#pragma unroll
    for (int mt = 0; mt < 4; mt++) {
        int row = wm + mt * 16 + ((mat & 1) << 3) + lr;
        uint32_t off = (uint32_t)(row * 128 + kt * 32 + ((mat >> 1) << 4));
        ldsm4(A[mt], a_base + sw128(off));
    }
#pragma unroll
    for (int nt = 0; nt < 2; nt++) {
        int row = wn + nt * 16 + ((mat >> 1) << 3) + lr;
        uint32_t off = (uint32_t)(row * 128 + kt * 32 + ((mat & 1) << 4));
        ldsm4(B[nt], b_base + sw128(off));
    }
}

// ---------------------------------------------------------------------------
// Main GEMM: C[128,256] = A @ B^T; fp16 mma with fp16 acc, promoted to fp32
// master accumulators every BK=64 (4 mma chunks). 16 warps, warp tile 64x32.
// ---------------------------------------------------------------------------
__global__ void __launch_bounds__(NTHREADS, 1)
ternary_gemm_kernel(const float* __restrict__ scale_p,
                    const float* __restrict__ bias,
                    float* __restrict__ out) {
    extern __shared__ char smem[];
    const uint32_t sb = smem_u32(smem);
    const int tid = threadIdx.x;
    const int lane = tid & 31, wid = tid >> 5;
    const int m0 = blockIdx.y * BM;
    const int n0 = blockIdx.x * BN;
    const int wm = (wid & 1) * 64;        // 2 m-warps
    const int wn = (wid >> 1) * 32;       // 8 n-warps

    // fp32 master accumulators: [mt][n8][4]
    float acc[4][4][4];
#pragma unroll
    for (int i = 0; i < 4; i++)
#pragma unroll
        for (int j = 0; j < 4; j++)
#pragma unroll
            for (int c = 0; c < 4; c++) acc[i][j][c] = 0.0f;

    // ---- pipeline prologue ----
#pragma unroll
    for (int s = 0; s < STAGES - 1; s++) {
        load_stage(sb + s * STAGE_BYTES, m0, n0, s * BK, tid);
        asm volatile("cp.async.commit_group;" ::: "memory");
    }
    asm volatile("cp.async.wait_group %0;" :: "n"(STAGES - 2) : "memory");
    __syncthreads();

    int rs = 0, ws = STAGES - 1;

    for (int k = 0; k < KT; k++) {
        // prefetch stage k+STAGES-1
        if (k + STAGES - 1 < KT)
            load_stage(sb + ws * STAGE_BYTES, m0, n0, (k + STAGES - 1) * BK, tid);
        asm volatile("cp.async.commit_group;" ::: "memory");

        const uint32_t abase = sb + rs * STAGE_BYTES;
        const uint32_t bbase = abase + A_BYTES;

        // fp16 chunk accumulators (zeroed per k-iter)
        uint32_t accH[4][4][2];
#pragma unroll
        for (int i = 0; i < 4; i++)
#pragma unroll
            for (int j = 0; j < 4; j++) { accH[i][j][0] = 0u; accH[i][j][1] = 0u; }

        uint32_t Af[2][4][4], Bf[2][2][4];
        load_frags(abase, bbase, 0, wm, wn, lane, Af[0], Bf[0]);
#pragma unroll
        for (int kt = 0; kt < 4; kt++) {
            if (kt < 3)
                load_frags(abase, bbase, kt + 1, wm, wn, lane, Af[(kt + 1) & 1], Bf[(kt + 1) & 1]);
            const int cur = kt & 1;
#pragma unroll
            for (int mt = 0; mt < 4; mt++) {
#pragma unroll
                for (int nt = 0; nt < 2; nt++) {
                    mma16816_h(accH[mt][nt * 2],     Af[cur][mt], Bf[cur][nt][0], Bf[cur][nt][1]);
                    mma16816_h(accH[mt][nt * 2 + 1], Af[cur][mt], Bf[cur][nt][2], Bf[cur][nt][3]);
                }
            }
        }

        // promote fp16 chunk sums into fp32 master accumulators
#pragma unroll
        for (int mt = 0; mt < 4; mt++) {
#pragma unroll
            for (int n8 = 0; n8 < 4; n8++) {
                float2 lo = __half22float2(*(const __half2*)&accH[mt][n8][0]);
                float2 hi = __half22float2(*(const __half2*)&accH[mt][n8][1]);
                acc[mt][n8][0] += lo.x;
                acc[mt][n8][1] += lo.y;
                acc[mt][n8][2] += hi.x;
                acc[mt][n8][3] += hi.y;
            }
        }

        ws = rs;
        rs = (rs + 1) % STAGES;
        asm volatile("cp.async.wait_group %0;" :: "n"(STAGES - 2) : "memory");
        __syncthreads();
    }

    // ---- epilogue: y = scale * acc + bias, direct float2 stores ----
    const float scale = __ldg(scale_p);
#pragma unroll
    for (int mt = 0; mt < 4; mt++) {
        const int row = m0 + wm + mt * 16 + (lane >> 2);
#pragma unroll
        for (int n8 = 0; n8 < 4; n8++) {
            const int col = n0 + wn + n8 * 8 + (lane & 3) * 2;
            const float2 bb = *(const float2*)(bias + col);
            float2 v0, v1;
            v0.x = fmaf(scale, acc[mt][n8][0], bb.x);
            v0.y = fmaf(scale, acc[mt][n8][1], bb.y);
            v1.x = fmaf(scale, acc[mt][n8][2], bb.x);
            v1.y = fmaf(scale, acc[mt][n8][3], bb.y);
            *(float2*)(out + (size_t)row * ODIM + col)       = v0;
            *(float2*)(out + (size_t)(row + 8) * ODIM + col) = v1;
        }
    }
}

// ---------------------------------------------------------------------------
// Launch
// ---------------------------------------------------------------------------
extern "C" void kernel_launch(void* const* d_in, const int* in_sizes, int n_in,
                              void* d_out, int out_size) {
    const float* x     = (const float*)d_in[0];
    const int*   pm    = (const int*)d_in[1];
    const int*   nm    = (const int*)d_in[2];
    const float* scale = (const float*)d_in[3];
    const float* bias  = (const float*)d_in[4];
    float* out = (float*)d_out;

    (void)in_sizes; (void)n_in; (void)out_size;

    tofp16_x_kernel<<<(int)(((size_t)TOKENS * KDIM) / (256 * 8)), 256>>>(x);
    unpack_w_kernel<<<(ODIM * (KDIM / 8)) / 256, 256>>>(pm, nm);

    cudaFuncSetAttribute(ternary_gemm_kernel,
                         cudaFuncAttributeMaxDynamicSharedMemorySize, SMEM_TOTAL);
    dim3 grid(ODIM / BN, TOKENS / BM);
    ternary_gemm_kernel<<<grid, NTHREADS, SMEM_TOTAL>>>(scale, bias, out);
}